// round 1
// baseline (speedup 1.0000x reference)
#include <cuda_runtime.h>
#include <math.h>

#define S_LEN   2048
#define D_IN    4096
#define D_OUTD  4096
#define M_TOK   8192
#define NEXP    4
#define RK      16
#define ER      64          // E * R
#define SCALING 2.0f        // 32.0 / 16.0

// ---------------- scratch (no allocations allowed) ----------------
__device__ float g_lbt[ER * D_OUTD];     // lora_B transposed: [er][o]   (1 MB)
__device__ float g_gate[M_TOK * NEXP];   // softmax gates                (128 KB)
__device__ float g_c[M_TOK * ER];        // gate-scaled h (A-matrix of lora tail GEMM, K=64) (2 MB)

// ---------------- P1: transpose lora_B [E][D_OUT][R] -> [e*R+r][D_OUT] ----------------
__global__ void prep_lbt(const float* __restrict__ lora_B) {
    int idx = blockIdx.x * blockDim.x + threadIdx.x;
    if (idx >= ER * D_OUTD) return;
    int j = idx / D_OUTD;          // er index
    int o = idx - j * D_OUTD;
    int e = j >> 4;
    int r = j & 15;
    g_lbt[idx] = lora_B[((size_t)e * D_OUTD + o) * RK + r];
}

// ---------------- P2: router logits + softmax (1 warp per token) ----------------
__global__ __launch_bounds__(256) void prep_gate(
    const float* __restrict__ x,
    const float* __restrict__ w_img, const float* __restrict__ b_img,
    const float* __restrict__ w_txt, const float* __restrict__ b_txt)
{
    int warp = threadIdx.x >> 5;
    int lane = threadIdx.x & 31;
    int t = blockIdx.x * 8 + warp;
    if (t >= M_TOK) return;
    int s = t & (S_LEN - 1);
    const float* wr = (s < 32) ? w_img : w_txt;
    const float* br = (s < 32) ? b_img : b_txt;
    const float* xp = x + (size_t)t * D_IN;

    float a0 = 0.f, a1 = 0.f, a2 = 0.f, a3 = 0.f;
    for (int k = lane; k < D_IN; k += 32) {
        float xv = xp[k];
        a0 = fmaf(xv, wr[k],            a0);
        a1 = fmaf(xv, wr[D_IN   + k],   a1);
        a2 = fmaf(xv, wr[2*D_IN + k],   a2);
        a3 = fmaf(xv, wr[3*D_IN + k],   a3);
    }
    #pragma unroll
    for (int off = 16; off; off >>= 1) {
        a0 += __shfl_down_sync(0xffffffffu, a0, off);
        a1 += __shfl_down_sync(0xffffffffu, a1, off);
        a2 += __shfl_down_sync(0xffffffffu, a2, off);
        a3 += __shfl_down_sync(0xffffffffu, a3, off);
    }
    if (lane == 0) {
        float l0 = a0 + br[0], l1 = a1 + br[1], l2 = a2 + br[2], l3 = a3 + br[3];
        float mx = fmaxf(fmaxf(l0, l1), fmaxf(l2, l3));
        float e0 = expf(l0 - mx), e1 = expf(l1 - mx), e2 = expf(l2 - mx), e3 = expf(l3 - mx);
        float inv = 1.0f / (e0 + e1 + e2 + e3);
        g_gate[t * 4 + 0] = e0 * inv;
        g_gate[t * 4 + 1] = e1 * inv;
        g_gate[t * 4 + 2] = e2 * inv;
        g_gate[t * 4 + 3] = e3 * inv;
    }
}

// ---------------- P3: h = x @ lora_A^T, scaled by gate*SCALING -> g_c ----------------
// 64x64 tile, BK=16, 256 threads, 4x4 microtile, double buffered.
__global__ __launch_bounds__(256) void prep_c(
    const float* __restrict__ x, const float* __restrict__ lora_A)
{
    __shared__ float As[2][16][64];
    __shared__ float Ws[2][16][64];
    int tid = threadIdx.x;
    int m0 = blockIdx.x * 64;

    int lrow = tid >> 2;            // 0..63
    int lk   = (tid & 3) * 4;       // 0,4,8,12
    const float* Ap = x      + (size_t)(m0 + lrow) * D_IN + lk;
    const float* Wp = lora_A + (size_t)lrow        * D_IN + lk;   // lora_A flat [64][D_IN]

    int ty = tid >> 4;              // 0..15 -> m = ty*4
    int tx = tid & 15;              // 0..15 -> n = tx*4

    float acc[4][4];
    #pragma unroll
    for (int i = 0; i < 4; i++)
        #pragma unroll
        for (int j = 0; j < 4; j++) acc[i][j] = 0.f;

    float4 ra = *(const float4*)Ap;
    float4 rw = *(const float4*)Wp;
    As[0][lk+0][lrow] = ra.x; As[0][lk+1][lrow] = ra.y; As[0][lk+2][lrow] = ra.z; As[0][lk+3][lrow] = ra.w;
    Ws[0][lk+0][lrow] = rw.x; Ws[0][lk+1][lrow] = rw.y; Ws[0][lk+2][lrow] = rw.z; Ws[0][lk+3][lrow] = rw.w;
    __syncthreads();

    const int NIT = D_IN / 16;      // 256
    int buf = 0;
    for (int kt = 1; kt <= NIT; kt++) {
        float4 na, nw;
        if (kt < NIT) {
            na = *(const float4*)(Ap + kt * 16);
            nw = *(const float4*)(Wp + kt * 16);
        }
        #pragma unroll
        for (int k = 0; k < 16; k++) {
            float a[4], b[4];
            *(float4*)a = *(const float4*)&As[buf][k][ty * 4];
            *(float4*)b = *(const float4*)&Ws[buf][k][tx * 4];
            #pragma unroll
            for (int i = 0; i < 4; i++)
                #pragma unroll
                for (int j = 0; j < 4; j++)
                    acc[i][j] = fmaf(a[i], b[j], acc[i][j]);
        }
        if (kt < NIT) {
            int nb = buf ^ 1;
            As[nb][lk+0][lrow] = na.x; As[nb][lk+1][lrow] = na.y; As[nb][lk+2][lrow] = na.z; As[nb][lk+3][lrow] = na.w;
            Ws[nb][lk+0][lrow] = nw.x; Ws[nb][lk+1][lrow] = nw.y; Ws[nb][lk+2][lrow] = nw.z; Ws[nb][lk+3][lrow] = nw.w;
        }
        __syncthreads();
        buf ^= 1;
    }

    #pragma unroll
    for (int i = 0; i < 4; i++) {
        int t = m0 + ty * 4 + i;
        #pragma unroll
        for (int j = 0; j < 4; j++) {
            int col = tx * 4 + j;                       // er index 0..63
            float gate = g_gate[t * 4 + (col >> 4)];    // e = col/16
            g_c[(size_t)t * ER + col] = acc[i][j] * gate * SCALING;
        }
    }
}

// ---------------- Main: out = x @ w_base^T + b_base + g_c @ g_lbt ----------------
// 128x128 tile, BK=8, 256 threads, 8x8 microtile, smem double-buffered,
// then K=64 LoRA tail loop, then bias + single writeback.
__global__ __launch_bounds__(256) void gemm_main(
    const float* __restrict__ A, const float* __restrict__ W,
    const float* __restrict__ bias, float* __restrict__ out)
{
    __shared__ float As[2][8][128];
    __shared__ float Bs[2][8][128];
    int tid = threadIdx.x;
    int m0 = blockIdx.y * 128;
    int n0 = blockIdx.x * 128;

    int lrow = tid >> 1;            // 0..127
    int lk   = (tid & 1) * 4;       // 0 or 4
    const float* Ap = A + (size_t)(m0 + lrow) * D_IN + lk;
    const float* Wp = W + (size_t)(n0 + lrow) * D_IN + lk;

    int ty = tid >> 4;              // 0..15 -> m = ty*8
    int tx = tid & 15;              // 0..15 -> n = tx*8

    float acc[8][8];
    #pragma unroll
    for (int i = 0; i < 8; i++)
        #pragma unroll
        for (int j = 0; j < 8; j++) acc[i][j] = 0.f;

    float4 ra = *(const float4*)Ap;
    float4 rb = *(const float4*)Wp;
    As[0][lk+0][lrow] = ra.x; As[0][lk+1][lrow] = ra.y; As[0][lk+2][lrow] = ra.z; As[0][lk+3][lrow] = ra.w;
    Bs[0][lk+0][lrow] = rb.x; Bs[0][lk+1][lrow] = rb.y; Bs[0][lk+2][lrow] = rb.z; Bs[0][lk+3][lrow] = rb.w;
    __syncthreads();

    const int NIT = D_IN / 8;       // 512
    int buf = 0;
    for (int kt = 1; kt <= NIT; kt++) {
        float4 na, nb4;
        if (kt < NIT) {
            na  = *(const float4*)(Ap + kt * 8);
            nb4 = *(const float4*)(Wp + kt * 8);
        }
        #pragma unroll
        for (int k = 0; k < 8; k++) {
            float a[8], b[8];
            *(float4*)&a[0] = *(const float4*)&As[buf][k][ty * 8];
            *(float4*)&a[4] = *(const float4*)&As[buf][k][ty * 8 + 4];
            *(float4*)&b[0] = *(const float4*)&Bs[buf][k][tx * 8];
            *(float4*)&b[4] = *(const float4*)&Bs[buf][k][tx * 8 + 4];
            #pragma unroll
            for (int i = 0; i < 8; i++)
                #pragma unroll
                for (int j = 0; j < 8; j++)
                    acc[i][j] = fmaf(a[i], b[j], acc[i][j]);
        }
        if (kt < NIT) {
            int nb = buf ^ 1;
            As[nb][lk+0][lrow] = na.x;  As[nb][lk+1][lrow] = na.y;  As[nb][lk+2][lrow] = na.z;  As[nb][lk+3][lrow] = na.w;
            Bs[nb][lk+0][lrow] = nb4.x; Bs[nb][lk+1][lrow] = nb4.y; Bs[nb][lk+2][lrow] = nb4.z; Bs[nb][lk+3][lrow] = nb4.w;
        }
        __syncthreads();
        buf ^= 1;
    }

    // -------- LoRA tail: K2 = 64, A-role = g_c [8192][64], B-role = g_lbt [64][4096] --------
    int brow = tid >> 5;            // 0..7
    int bcol = (tid & 31) * 4;      // 0..124
    for (int kt = 0; kt < 8; kt++) {
        __syncthreads();
        float4 ca = *(const float4*)(g_c + (size_t)(m0 + lrow) * ER + kt * 8 + lk);
        As[0][lk+0][lrow] = ca.x; As[0][lk+1][lrow] = ca.y; As[0][lk+2][lrow] = ca.z; As[0][lk+3][lrow] = ca.w;
        float4 lb = *(const float4*)(g_lbt + (size_t)(kt * 8 + brow) * D_OUTD + n0 + bcol);
        *(float4*)&Bs[0][brow][bcol] = lb;
        __syncthreads();
        #pragma unroll
        for (int k = 0; k < 8; k++) {
            float a[8], b[8];
            *(float4*)&a[0] = *(const float4*)&As[0][k][ty * 8];
            *(float4*)&a[4] = *(const float4*)&As[0][k][ty * 8 + 4];
            *(float4*)&b[0] = *(const float4*)&Bs[0][k][tx * 8];
            *(float4*)&b[4] = *(const float4*)&Bs[0][k][tx * 8 + 4];
            #pragma unroll
            for (int i = 0; i < 8; i++)
                #pragma unroll
                for (int j = 0; j < 8; j++)
                    acc[i][j] = fmaf(a[i], b[j], acc[i][j]);
        }
    }

    // -------- bias + writeback --------
    #pragma unroll
    for (int i = 0; i < 8; i++) {
        int m = m0 + ty * 8 + i;
        #pragma unroll
        for (int j4 = 0; j4 < 2; j4++) {
            int n = n0 + tx * 8 + j4 * 4;
            float4 o;
            o.x = acc[i][j4*4+0] + bias[n+0];
            o.y = acc[i][j4*4+1] + bias[n+1];
            o.z = acc[i][j4*4+2] + bias[n+2];
            o.w = acc[i][j4*4+3] + bias[n+3];
            *(float4*)&out[(size_t)m * D_OUTD + n] = o;
        }
    }
}

// ---------------- launch ----------------
extern "C" void kernel_launch(void* const* d_in, const int* in_sizes, int n_in,
                              void* d_out, int out_size) {
    const float* x      = (const float*)d_in[0];
    const float* w_base = (const float*)d_in[1];
    const float* b_base = (const float*)d_in[2];
    const float* w_ri   = (const float*)d_in[3];
    const float* b_ri   = (const float*)d_in[4];
    const float* w_rt   = (const float*)d_in[5];
    const float* b_rt   = (const float*)d_in[6];
    const float* lora_A = (const float*)d_in[7];
    const float* lora_B = (const float*)d_in[8];
    float* out = (float*)d_out;

    prep_lbt <<<(ER * D_OUTD + 255) / 256, 256>>>(lora_B);
    prep_gate<<<M_TOK / 8, 256>>>(x, w_ri, b_ri, w_rt, b_rt);
    prep_c   <<<M_TOK / 64, 256>>>(x, lora_A);

    dim3 grid(D_OUTD / 128, M_TOK / 128);
    gemm_main<<<grid, 256>>>(x, w_base, b_base, out);
}

// round 3
// speedup vs baseline: 3.0379x; 3.0379x over previous
#include <cuda_runtime.h>
#include <cstdint>
#include <math.h>

#define S_LEN   2048
#define D_IN    4096
#define D_OUTD  4096
#define M_TOK   8192
#define RK      16
#define ER      64
#define SCALING 2.0f

// ---- mma.sync tf32 gemm config ----
#define BM      128
#define BN      128
#define BK      32
#define STAGES  4
#define NIT_TOT 130                     // 4096/32 + 64/32
#define A_FLOATS (BM*BK)                // 4096 floats = 16KB
#define STAGE_FLOATS (2*A_FLOATS)       // A + B
#define SMEM_TOTAL (STAGES*STAGE_FLOATS*4)  // 131072 B

// ---------------- scratch ----------------
__device__ __align__(1024) float g_lbt2[D_OUTD * ER];  // [o][er]  K-major like w_base
__device__ float g_gate[M_TOK * 4];
__device__ __align__(1024) float g_c[M_TOK * ER];      // [m][er]  K-major like x

// ---------------- helpers ----------------
static __device__ __forceinline__ uint32_t smem_u32(const void* p) {
    uint32_t a;
    asm("{ .reg .u64 t; cvta.to.shared.u64 t, %1; cvt.u32.u64 %0, t; }" : "=r"(a) : "l"(p));
    return a;
}
#define CP_ASYNC16(dst, src) \
    asm volatile("cp.async.cg.shared.global [%0], [%1], 16;" :: "r"(dst), "l"(src) : "memory")
#define CP_COMMIT() asm volatile("cp.async.commit_group;" ::: "memory")
#define CP_WAIT2()  asm volatile("cp.async.wait_group 2;" ::: "memory")

static __device__ __forceinline__ uint32_t f2tf(float f) {
    uint32_t u;
    asm("cvt.rna.tf32.f32 %0, %1;" : "=r"(u) : "f"(f));
    return u;
}
static __device__ __forceinline__ void mma_tf32(
    float& c0, float& c1, float& c2, float& c3,
    uint32_t a0, uint32_t a1, uint32_t a2, uint32_t a3,
    uint32_t b0, uint32_t b1)
{
    asm volatile(
        "mma.sync.aligned.m16n8k8.row.col.f32.tf32.tf32.f32 "
        "{%0,%1,%2,%3}, {%4,%5,%6,%7}, {%8,%9}, {%0,%1,%2,%3};"
        : "+f"(c0), "+f"(c1), "+f"(c2), "+f"(c3)
        : "r"(a0), "r"(a1), "r"(a2), "r"(a3), "r"(b0), "r"(b1));
}

// ---------------- P1: lora_B [E][O][R] -> g_lbt2 [O][ER] ----------------
__global__ void prep_lbt(const float* __restrict__ lora_B) {
    int idx = blockIdx.x * blockDim.x + threadIdx.x;
    if (idx >= D_OUTD * ER) return;
    int o = idx >> 6;
    int j = idx & 63;
    g_lbt2[idx] = lora_B[((size_t)(j >> 4) * D_OUTD + o) * RK + (j & 15)];
}

// ---------------- P2: router + softmax ----------------
__global__ __launch_bounds__(256) void prep_gate(
    const float* __restrict__ x,
    const float* __restrict__ w_img, const float* __restrict__ b_img,
    const float* __restrict__ w_txt, const float* __restrict__ b_txt)
{
    int warp = threadIdx.x >> 5, lane = threadIdx.x & 31;
    int t = blockIdx.x * 8 + warp;
    if (t >= M_TOK) return;
    int s = t & (S_LEN - 1);
    const float* wr = (s < 32) ? w_img : w_txt;
    const float* br = (s < 32) ? b_img : b_txt;
    const float* xp = x + (size_t)t * D_IN;
    float a0 = 0.f, a1 = 0.f, a2 = 0.f, a3 = 0.f;
    for (int k = lane; k < D_IN; k += 32) {
        float xv = xp[k];
        a0 = fmaf(xv, wr[k], a0);
        a1 = fmaf(xv, wr[D_IN + k], a1);
        a2 = fmaf(xv, wr[2 * D_IN + k], a2);
        a3 = fmaf(xv, wr[3 * D_IN + k], a3);
    }
    #pragma unroll
    for (int off = 16; off; off >>= 1) {
        a0 += __shfl_down_sync(0xffffffffu, a0, off);
        a1 += __shfl_down_sync(0xffffffffu, a1, off);
        a2 += __shfl_down_sync(0xffffffffu, a2, off);
        a3 += __shfl_down_sync(0xffffffffu, a3, off);
    }
    if (lane == 0) {
        float l0 = a0 + br[0], l1 = a1 + br[1], l2 = a2 + br[2], l3 = a3 + br[3];
        float mx = fmaxf(fmaxf(l0, l1), fmaxf(l2, l3));
        float e0 = expf(l0 - mx), e1 = expf(l1 - mx), e2 = expf(l2 - mx), e3 = expf(l3 - mx);
        float inv = 1.0f / (e0 + e1 + e2 + e3);
        g_gate[t * 4 + 0] = e0 * inv; g_gate[t * 4 + 1] = e1 * inv;
        g_gate[t * 4 + 2] = e2 * inv; g_gate[t * 4 + 3] = e3 * inv;
    }
}

// ---------------- P3: g_c = (x @ lora_A^T) * gate * SCALING ----------------
__global__ __launch_bounds__(256) void prep_c(
    const float* __restrict__ x, const float* __restrict__ lora_A)
{
    __shared__ float As[2][16][64];
    __shared__ float Ws[2][16][64];
    int tid = threadIdx.x;
    int m0 = blockIdx.x * 64;
    int lrow = tid >> 2, lk = (tid & 3) * 4;
    const float* Ap = x      + (size_t)(m0 + lrow) * D_IN + lk;
    const float* Wp = lora_A + (size_t)lrow        * D_IN + lk;
    int ty = tid >> 4, tx = tid & 15;

    float acc[4][4];
    #pragma unroll
    for (int i = 0; i < 4; i++)
        #pragma unroll
        for (int j = 0; j < 4; j++) acc[i][j] = 0.f;

    float4 ra = *(const float4*)Ap;
    float4 rw = *(const float4*)Wp;
    As[0][lk+0][lrow] = ra.x; As[0][lk+1][lrow] = ra.y; As[0][lk+2][lrow] = ra.z; As[0][lk+3][lrow] = ra.w;
    Ws[0][lk+0][lrow] = rw.x; Ws[0][lk+1][lrow] = rw.y; Ws[0][lk+2][lrow] = rw.z; Ws[0][lk+3][lrow] = rw.w;
    __syncthreads();

    const int NIT = D_IN / 16;
    int buf = 0;
    for (int kt = 1; kt <= NIT; kt++) {
        float4 na, nw;
        if (kt < NIT) { na = *(const float4*)(Ap + kt * 16); nw = *(const float4*)(Wp + kt * 16); }
        #pragma unroll
        for (int k = 0; k < 16; k++) {
            float a[4], b[4];
            *(float4*)a = *(const float4*)&As[buf][k][ty * 4];
            *(float4*)b = *(const float4*)&Ws[buf][k][tx * 4];
            #pragma unroll
            for (int i = 0; i < 4; i++)
                #pragma unroll
                for (int j = 0; j < 4; j++)
                    acc[i][j] = fmaf(a[i], b[j], acc[i][j]);
        }
        if (kt < NIT) {
            int nb = buf ^ 1;
            As[nb][lk+0][lrow] = na.x; As[nb][lk+1][lrow] = na.y; As[nb][lk+2][lrow] = na.z; As[nb][lk+3][lrow] = na.w;
            Ws[nb][lk+0][lrow] = nw.x; Ws[nb][lk+1][lrow] = nw.y; Ws[nb][lk+2][lrow] = nw.z; Ws[nb][lk+3][lrow] = nw.w;
        }
        __syncthreads();
        buf ^= 1;
    }
    #pragma unroll
    for (int i = 0; i < 4; i++) {
        int t = m0 + ty * 4 + i;
        #pragma unroll
        for (int j = 0; j < 4; j++) {
            int col = tx * 4 + j;
            float gate = g_gate[t * 4 + (col >> 4)];
            g_c[(size_t)t * ER + col] = acc[i][j] * gate * SCALING;
        }
    }
}

// ---------------- Main GEMM: mma.sync tf32, K = 4096 + 64 folded LoRA ----------------
// Shared layout per tile row: float idx = row*32 + (k ^ ((row&7)<<2))  (conflict-free)
static __device__ __forceinline__ void load_chunk(
    int tid, uint32_t stage_base,                    // byte addr of stage
    const float* __restrict__ ap, int astride,
    const float* __restrict__ bp, int bstride)
{
    #pragma unroll
    for (int i = 0; i < 4; i++) {
        int idx = i * 256 + tid;                     // 0..1023
        int row = idx >> 3, g = idx & 7;
        uint32_t off = (row * 32 + ((g ^ (row & 7)) * 4)) * 4;
        CP_ASYNC16(stage_base + off, ap + (size_t)row * astride + g * 4);
    }
    uint32_t bb = stage_base + A_FLOATS * 4;
    #pragma unroll
    for (int i = 0; i < 4; i++) {
        int idx = i * 256 + tid;
        int row = idx >> 3, g = idx & 7;
        uint32_t off = (row * 32 + ((g ^ (row & 7)) * 4)) * 4;
        CP_ASYNC16(bb + off, bp + (size_t)row * bstride + g * 4);
    }
    CP_COMMIT();
}

__global__ __launch_bounds__(256, 1) void gemm_mma(
    const float* __restrict__ x, const float* __restrict__ w,
    const float* __restrict__ bias, float* __restrict__ out)
{
    extern __shared__ __align__(1024) float smem[];
    uint32_t sb = smem_u32(smem);
    int tid = threadIdx.x;
    int warp = tid >> 5, lane = tid & 31;
    int wm = warp >> 2;          // 0..1  (64 rows each)
    int wn = warp & 3;           // 0..3  (32 cols each)
    int r = lane >> 2;           // 0..7
    int cq = lane & 3;           // 0..3
    int m0 = blockIdx.y * BM;
    int n0 = blockIdx.x * BN;

    const float* abase_main = x + (size_t)m0 * D_IN;
    const float* bbase_main = w + (size_t)n0 * D_IN;
    const float* abase_lora = g_c + (size_t)m0 * ER;
    const float* bbase_lora = g_lbt2 + (size_t)n0 * ER;

    float acc[4][4][4];
    #pragma unroll
    for (int i = 0; i < 4; i++)
        #pragma unroll
        for (int j = 0; j < 4; j++)
            #pragma unroll
            for (int k = 0; k < 4; k++) acc[i][j][k] = 0.f;

    // prologue
    #pragma unroll
    for (int p = 0; p < STAGES - 1; p++)
        load_chunk(tid, sb + p * STAGE_FLOATS * 4,
                   abase_main + p * BK, D_IN, bbase_main + p * BK, D_IN);

    // precompute per-thread fragment base offsets (in floats)
    // A rows: wm*64 + mt*16 + r (+8);   swizzle xor value = (r&7)<<2 (same for +8)
    // B rows: wn*32 + nt*8 + r;
    int axor = (r & 7) << 2;

    for (int it = 0; it < NIT_TOT; it++) {
        int s = it & (STAGES - 1);
        CP_WAIT2();
        __syncthreads();

        int nxt = it + STAGES - 1;
        if (nxt < NIT_TOT) {
            int sn = nxt & (STAGES - 1);
            const float* ap; const float* bp; int as, bs2;
            if (nxt < 128) { ap = abase_main + nxt * BK; as = D_IN; bp = bbase_main + nxt * BK; bs2 = D_IN; }
            else           { ap = abase_lora + (nxt - 128) * BK; as = ER; bp = bbase_lora + (nxt - 128) * BK; bs2 = ER; }
            load_chunk(tid, sb + sn * STAGE_FLOATS * 4, ap, as, bp, bs2);
        } else {
            CP_COMMIT();
        }

        const float* sA = smem + s * STAGE_FLOATS;
        const float* sB = sA + A_FLOATS;

        #pragma unroll
        for (int ks = 0; ks < 4; ks++) {
            int k0 = ks * 8 + cq;
            int k1 = k0 + 4;
            uint32_t afr[4][4];
            #pragma unroll
            for (int mt = 0; mt < 4; mt++) {
                int row0 = wm * 64 + mt * 16 + r;
                const float* pa = sA + row0 * 32;
                afr[mt][0] = f2tf(pa[k0 ^ axor]);
                afr[mt][1] = f2tf(pa[256 + (k0 ^ axor)]);   // row0+8: +8*32 floats
                afr[mt][2] = f2tf(pa[k1 ^ axor]);
                afr[mt][3] = f2tf(pa[256 + (k1 ^ axor)]);
            }
            uint32_t bfr[4][2];
            #pragma unroll
            for (int nt = 0; nt < 4; nt++) {
                int nrow = wn * 32 + nt * 8 + r;
                const float* pb = sB + nrow * 32;
                int nxor = (nrow & 7) << 2;
                bfr[nt][0] = f2tf(pb[k0 ^ nxor]);
                bfr[nt][1] = f2tf(pb[k1 ^ nxor]);
            }
            #pragma unroll
            for (int mt = 0; mt < 4; mt++)
                #pragma unroll
                for (int nt = 0; nt < 4; nt++)
                    mma_tf32(acc[mt][nt][0], acc[mt][nt][1], acc[mt][nt][2], acc[mt][nt][3],
                             afr[mt][0], afr[mt][1], afr[mt][2], afr[mt][3],
                             bfr[nt][0], bfr[nt][1]);
        }
    }

    // epilogue: bias + store.  acc tile (mt,nt): c0=(r,n) c1=(r,n+1) c2=(r+8,n) c3=(r+8,n+1)
    float2 bb[4];
    #pragma unroll
    for (int nt = 0; nt < 4; nt++) {
        int n = n0 + wn * 32 + nt * 8 + cq * 2;
        bb[nt] = *(const float2*)&bias[n];
    }
    #pragma unroll
    for (int mt = 0; mt < 4; mt++) {
        int mA = m0 + wm * 64 + mt * 16 + r;
        #pragma unroll
        for (int h = 0; h < 2; h++) {
            int m = mA + h * 8;
            float* orow = out + (size_t)m * D_OUTD + n0 + wn * 32;
            #pragma unroll
            for (int nt = 0; nt < 4; nt++) {
                float2 v;
                v.x = acc[mt][nt][h * 2 + 0] + bb[nt].x;
                v.y = acc[mt][nt][h * 2 + 1] + bb[nt].y;
                *(float2*)&orow[nt * 8 + cq * 2] = v;
            }
        }
    }
}

// ---------------- launch ----------------
extern "C" void kernel_launch(void* const* d_in, const int* in_sizes, int n_in,
                              void* d_out, int out_size) {
    const float* x      = (const float*)d_in[0];
    const float* w_base = (const float*)d_in[1];
    const float* b_base = (const float*)d_in[2];
    const float* w_ri   = (const float*)d_in[3];
    const float* b_ri   = (const float*)d_in[4];
    const float* w_rt   = (const float*)d_in[5];
    const float* b_rt   = (const float*)d_in[6];
    const float* lora_A = (const float*)d_in[7];
    const float* lora_B = (const float*)d_in[8];
    float* out = (float*)d_out;

    cudaFuncSetAttribute(gemm_mma, cudaFuncAttributeMaxDynamicSharedMemorySize, SMEM_TOTAL);

    prep_lbt <<<(D_OUTD * ER + 255) / 256, 256>>>(lora_B);
    prep_gate<<<M_TOK / 8, 256>>>(x, w_ri, b_ri, w_rt, b_rt);
    prep_c   <<<M_TOK / 64, 256>>>(x, lora_A);

    dim3 grid(D_OUTD / BN, M_TOK / BM);   // 32 x 64
    gemm_mma<<<grid, 256, SMEM_TOTAL>>>(x, w_base, b_base, out);
}

// round 4
// speedup vs baseline: 5.2483x; 1.7276x over previous
#include <cuda_runtime.h>
#include <cuda_fp16.h>
#include <cstdint>
#include <math.h>

#define S_LEN   2048
#define D_IN    4096
#define D_OUTD  4096
#define M_TOK   8192
#define RK      16
#define ER      64
#define SCALING 2.0f

// ---- fp16 mma gemm config ----
#define BM      128
#define BN      128
#define BK      64
#define STAGES  4
#define NIT_TOT 65                       // 4096/64 main + 1 lora chunk (K=64)
#define A_BYTES (BM*BK*2)                // 16384
#define STAGE_BYTES (2*A_BYTES)          // 32768
#define SMEM_TOTAL (STAGES*STAGE_BYTES)  // 131072

// ---------------- scratch (half copies) ----------------
__device__ __align__(1024) __half g_xh[M_TOK * D_IN];     // 67 MB
__device__ __align__(1024) __half g_wh[D_OUTD * D_IN];    // 33.5 MB
__device__ __align__(1024) __half g_ch[M_TOK * ER];       // gate-scaled h
__device__ __align__(1024) __half g_lbth[D_OUTD * ER];    // lora_B re-laid [o][er]

// ---------------- helpers ----------------
static __device__ __forceinline__ uint32_t smem_u32(const void* p) {
    uint32_t a;
    asm("{ .reg .u64 t; cvta.to.shared.u64 t, %1; cvt.u32.u64 %0, t; }" : "=r"(a) : "l"(p));
    return a;
}
#define CP_ASYNC16(dst, src) \
    asm volatile("cp.async.cg.shared.global [%0], [%1], 16;" :: "r"(dst), "l"(src) : "memory")
#define CP_COMMIT() asm volatile("cp.async.commit_group;" ::: "memory")
#define CP_WAIT2()  asm volatile("cp.async.wait_group 2;" ::: "memory")

#define LDSM4(r0, r1, r2, r3, a) \
    asm volatile("ldmatrix.sync.aligned.m8n8.x4.shared.b16 {%0,%1,%2,%3}, [%4];" \
        : "=r"(r0), "=r"(r1), "=r"(r2), "=r"(r3) : "r"(a))

#define MMA16816(c0, c1, c2, c3, a0, a1, a2, a3, b0, b1) \
    asm volatile("mma.sync.aligned.m16n8k16.row.col.f32.f16.f16.f32 " \
        "{%0,%1,%2,%3}, {%4,%5,%6,%7}, {%8,%9}, {%0,%1,%2,%3};" \
        : "+f"(c0), "+f"(c1), "+f"(c2), "+f"(c3) \
        : "r"(a0), "r"(a1), "r"(a2), "r"(a3), "r"(b0), "r"(b1))

// ---------------- conv_w: w_base fp32 -> g_wh half ----------------
__global__ void conv_w(const float* __restrict__ w) {
    int i = blockIdx.x * blockDim.x + threadIdx.x;           // float4 index
    const int total = D_OUTD * D_IN / 4;
    for (; i < total; i += gridDim.x * blockDim.x) {
        float4 v = ((const float4*)w)[i];
        __half2 h[2];
        h[0] = __floats2half2_rn(v.x, v.y);
        h[1] = __floats2half2_rn(v.z, v.w);
        *(uint2*)&g_wh[(size_t)i * 4] = *(uint2*)h;
    }
}

// ---------------- prep_lbt: lora_B [E][O][R] -> g_lbth [O][ER] half ----------------
__global__ void prep_lbt(const float* __restrict__ lora_B) {
    int idx = blockIdx.x * blockDim.x + threadIdx.x;
    if (idx >= D_OUTD * ER) return;
    int o = idx >> 6;
    int j = idx & 63;
    g_lbth[idx] = __float2half_rn(lora_B[((size_t)(j >> 4) * D_OUTD + o) * RK + (j & 15)]);
}

// ---------------- fused prep: one pass over x ----------------
// Per 64-token block: write g_xh (half), compute h = x@lora_A^T, router logits,
// softmax gate, write g_ch = half(h * gate * SCALING).
__global__ __launch_bounds__(256) void prep_fused(
    const float* __restrict__ x, const float* __restrict__ lora_A,
    const float* __restrict__ w_img, const float* __restrict__ b_img,
    const float* __restrict__ w_txt, const float* __restrict__ b_txt)
{
    __shared__ float As[2][16][64];
    __shared__ float Ws[2][16][64];
    __shared__ float lg_s[64][4];
    int tid = threadIdx.x;
    int m0 = blockIdx.x * 64;
    int lrow = tid >> 2, lk = (tid & 3) * 4;
    const float* Ap = x      + (size_t)(m0 + lrow) * D_IN + lk;
    const float* Wp = lora_A + (size_t)lrow        * D_IN + lk;
    __half* xh_p = g_xh + (size_t)(m0 + lrow) * D_IN + lk;
    int ty = tid >> 4, tx = tid & 15;

    // router assignment for this thread's (token, expert)
    int tok = tid & 63;
    int e   = tid >> 6;
    int s   = (m0 + tok) & (S_LEN - 1);
    bool img = (s < 32);
    const float* wre = (img ? w_img : w_txt) + (size_t)e * D_IN;
    float lg = 0.f;

    float acc[4][4];
    #pragma unroll
    for (int i = 0; i < 4; i++)
        #pragma unroll
        for (int j = 0; j < 4; j++) acc[i][j] = 0.f;

    // preload chunk 0 (+ write xh for chunk 0)
    float4 ra = *(const float4*)Ap;
    float4 rw = *(const float4*)Wp;
    {
        __half2 h[2];
        h[0] = __floats2half2_rn(ra.x, ra.y);
        h[1] = __floats2half2_rn(ra.z, ra.w);
        *(uint2*)xh_p = *(uint2*)h;
    }
    As[0][lk+0][lrow] = ra.x; As[0][lk+1][lrow] = ra.y; As[0][lk+2][lrow] = ra.z; As[0][lk+3][lrow] = ra.w;
    Ws[0][lk+0][lrow] = rw.x; Ws[0][lk+1][lrow] = rw.y; Ws[0][lk+2][lrow] = rw.z; Ws[0][lk+3][lrow] = rw.w;
    __syncthreads();

    const int NIT = D_IN / 16;   // 256
    int buf = 0;
    for (int kt = 1; kt <= NIT; kt++) {
        float4 na, nw;
        if (kt < NIT) {
            na = *(const float4*)(Ap + kt * 16);
            nw = *(const float4*)(Wp + kt * 16);
            __half2 h[2];
            h[0] = __floats2half2_rn(na.x, na.y);
            h[1] = __floats2half2_rn(na.z, na.w);
            *(uint2*)(xh_p + kt * 16) = *(uint2*)h;
        }
        // h microtile on chunk kt-1
        #pragma unroll
        for (int k = 0; k < 16; k++) {
            float a[4], b[4];
            *(float4*)a = *(const float4*)&As[buf][k][ty * 4];
            *(float4*)b = *(const float4*)&Ws[buf][k][tx * 4];
            #pragma unroll
            for (int i = 0; i < 4; i++)
                #pragma unroll
                for (int j = 0; j < 4; j++)
                    acc[i][j] = fmaf(a[i], b[j], acc[i][j]);
        }
        // router logit on chunk kt-1
        {
            const float* wk = wre + (kt - 1) * 16;
            #pragma unroll
            for (int k = 0; k < 16; k++)
                lg = fmaf(As[buf][k][tok], wk[k], lg);
        }
        if (kt < NIT) {
            int nb = buf ^ 1;
            As[nb][lk+0][lrow] = na.x; As[nb][lk+1][lrow] = na.y; As[nb][lk+2][lrow] = na.z; As[nb][lk+3][lrow] = na.w;
            Ws[nb][lk+0][lrow] = nw.x; Ws[nb][lk+1][lrow] = nw.y; Ws[nb][lk+2][lrow] = nw.z; Ws[nb][lk+3][lrow] = nw.w;
        }
        __syncthreads();
        buf ^= 1;
    }

    lg_s[tok][e] = lg;
    __syncthreads();
    if (tid < 64) {
        int ss = (m0 + tid) & (S_LEN - 1);
        const float* bb = (ss < 32) ? b_img : b_txt;
        float l0 = lg_s[tid][0] + bb[0], l1 = lg_s[tid][1] + bb[1];
        float l2 = lg_s[tid][2] + bb[2], l3 = lg_s[tid][3] + bb[3];
        float mx = fmaxf(fmaxf(l0, l1), fmaxf(l2, l3));
        float e0 = expf(l0 - mx), e1 = expf(l1 - mx), e2 = expf(l2 - mx), e3 = expf(l3 - mx);
        float inv = 1.0f / (e0 + e1 + e2 + e3);
        lg_s[tid][0] = e0 * inv; lg_s[tid][1] = e1 * inv;
        lg_s[tid][2] = e2 * inv; lg_s[tid][3] = e3 * inv;
    }
    __syncthreads();

    #pragma unroll
    for (int i = 0; i < 4; i++) {
        int tl = ty * 4 + i;
        int t  = m0 + tl;
        #pragma unroll
        for (int j = 0; j < 4; j++) {
            int col = tx * 4 + j;
            float gate = lg_s[tl][col >> 4];
            g_ch[(size_t)t * ER + col] = __float2half_rn(acc[i][j] * gate * SCALING);
        }
    }
}

// ---------------- Main GEMM: fp16 mma.m16n8k16, K = 4096 + 64 folded LoRA ----------------
// smem tile: [rows][BK halves], 128B/row; 16B-group swizzle g' = g ^ (row&7)
static __device__ __forceinline__ void load_chunk(
    int tid, uint32_t stage_base,
    const __half* __restrict__ ap, int astride,
    const __half* __restrict__ bp, int bstride)
{
    #pragma unroll
    for (int i = 0; i < 4; i++) {
        int idx = i * 256 + tid;                 // 0..1023
        int row = idx >> 3, g = idx & 7;
        CP_ASYNC16(stage_base + row * 128 + ((g ^ (row & 7)) * 16),
                   ap + (size_t)row * astride + g * 8);
    }
    uint32_t bb = stage_base + A_BYTES;
    #pragma unroll
    for (int i = 0; i < 4; i++) {
        int idx = i * 256 + tid;
        int row = idx >> 3, g = idx & 7;
        CP_ASYNC16(bb + row * 128 + ((g ^ (row & 7)) * 16),
                   bp + (size_t)row * bstride + g * 8);
    }
    CP_COMMIT();
}

__global__ __launch_bounds__(256, 1) void gemm_h(
    const float* __restrict__ bias, float* __restrict__ out)
{
    extern __shared__ __align__(1024) char smem[];
    uint32_t sb = smem_u32(smem);
    int tid = threadIdx.x;
    int warp = tid >> 5, lane = tid & 31;
    int wm = warp >> 2;          // 0..1  (64 rows)
    int wn = warp & 3;           // 0..3  (32 cols)
    int r = lane >> 2;           // 0..7
    int cq = lane & 3;           // 0..3
    int m0 = blockIdx.y * BM;
    int n0 = blockIdx.x * BN;

    const __half* abase_main = g_xh + (size_t)m0 * D_IN;
    const __half* bbase_main = g_wh + (size_t)n0 * D_IN;
    const __half* abase_lora = g_ch + (size_t)m0 * ER;
    const __half* bbase_lora = g_lbth + (size_t)n0 * ER;

    float acc[4][4][4];
    #pragma unroll
    for (int i = 0; i < 4; i++)
        #pragma unroll
        for (int j = 0; j < 4; j++)
            #pragma unroll
            for (int k = 0; k < 4; k++) acc[i][j][k] = 0.f;

    // prologue
    #pragma unroll
    for (int p = 0; p < STAGES - 1; p++)
        load_chunk(tid, sb + p * STAGE_BYTES,
                   abase_main + p * BK, D_IN, bbase_main + p * BK, D_IN);

    // per-thread ldmatrix address components
    int ksel = lane >> 4;        // 0..1
    int swm  = lane & 7;         // swizzle mask for this thread's rows
    int rowl = lane & 15;

    for (int it = 0; it < NIT_TOT; it++) {
        int s = it & (STAGES - 1);
        CP_WAIT2();
        __syncthreads();

        int nxt = it + STAGES - 1;
        if (nxt < NIT_TOT) {
            int sn = nxt & (STAGES - 1);
            if (nxt < 64)
                load_chunk(tid, sb + sn * STAGE_BYTES,
                           abase_main + nxt * BK, D_IN, bbase_main + nxt * BK, D_IN);
            else
                load_chunk(tid, sb + sn * STAGE_BYTES,
                           abase_lora, ER, bbase_lora, ER);
        } else {
            CP_COMMIT();
        }

        uint32_t st = sb + s * STAGE_BYTES;
        uint32_t aRow = st + (wm * 64 + rowl) * 128;
        uint32_t bRow = st + A_BYTES + (wn * 32 + rowl) * 128;

        #pragma unroll
        for (int ks = 0; ks < 4; ks++) {
            uint32_t ko = (uint32_t)(((ks * 2 + ksel) ^ swm) * 16);
            uint32_t afr[4][4];
            #pragma unroll
            for (int mt = 0; mt < 4; mt++)
                LDSM4(afr[mt][0], afr[mt][1], afr[mt][2], afr[mt][3],
                      aRow + mt * 2048 + ko);
            uint32_t bfr[4][2];
            #pragma unroll
            for (int ng = 0; ng < 2; ng++) {
                uint32_t t0, t1, t2, t3;
                LDSM4(t0, t1, t2, t3, bRow + ng * 2048 + ko);
                bfr[2*ng+0][0] = t0; bfr[2*ng+0][1] = t2;
                bfr[2*ng+1][0] = t1; bfr[2*ng+1][1] = t3;
            }
            #pragma unroll
            for (int mt = 0; mt < 4; mt++)
                #pragma unroll
                for (int nt = 0; nt < 4; nt++)
                    MMA16816(acc[mt][nt][0], acc[mt][nt][1], acc[mt][nt][2], acc[mt][nt][3],
                             afr[mt][0], afr[mt][1], afr[mt][2], afr[mt][3],
                             bfr[nt][0], bfr[nt][1]);
        }
    }

    // epilogue: bias + store. tile (mt,nt): c0=(r,n) c1=(r,n+1) c2=(r+8,n) c3=(r+8,n+1)
    float2 bb[4];
    #pragma unroll
    for (int nt = 0; nt < 4; nt++) {
        int n = n0 + wn * 32 + nt * 8 + cq * 2;
        bb[nt] = *(const float2*)&bias[n];
    }
    #pragma unroll
    for (int mt = 0; mt < 4; mt++) {
        int mA = m0 + wm * 64 + mt * 16 + r;
        #pragma unroll
        for (int h = 0; h < 2; h++) {
            int m = mA + h * 8;
            float* orow = out + (size_t)m * D_OUTD + n0 + wn * 32;
            #pragma unroll
            for (int nt = 0; nt < 4; nt++) {
                float2 v;
                v.x = acc[mt][nt][h * 2 + 0] + bb[nt].x;
                v.y = acc[mt][nt][h * 2 + 1] + bb[nt].y;
                *(float2*)&orow[nt * 8 + cq * 2] = v;
            }
        }
    }
}

// ---------------- launch ----------------
extern "C" void kernel_launch(void* const* d_in, const int* in_sizes, int n_in,
                              void* d_out, int out_size) {
    const float* x      = (const float*)d_in[0];
    const float* w_base = (const float*)d_in[1];
    const float* b_base = (const float*)d_in[2];
    const float* w_ri   = (const float*)d_in[3];
    const float* b_ri   = (const float*)d_in[4];
    const float* w_rt   = (const float*)d_in[5];
    const float* b_rt   = (const float*)d_in[6];
    const float* lora_A = (const float*)d_in[7];
    const float* lora_B = (const float*)d_in[8];
    float* out = (float*)d_out;

    cudaFuncSetAttribute(gemm_h, cudaFuncAttributeMaxDynamicSharedMemorySize, SMEM_TOTAL);

    conv_w    <<<4096, 256>>>(w_base);
    prep_lbt  <<<(D_OUTD * ER + 255) / 256, 256>>>(lora_B);
    prep_fused<<<M_TOK / 64, 256>>>(x, lora_A, w_ri, b_ri, w_rt, b_rt);

    dim3 grid(D_OUTD / BN, M_TOK / BM);   // 32 x 64
    gemm_h<<<grid, 256, SMEM_TOTAL>>>(b_base, out);
}